// round 15
// baseline (speedup 1.0000x reference)
#include <cuda_runtime.h>
#include <cuda_bf16.h>

typedef unsigned long long u64;

// ============================================================================
// Problem constants
// ============================================================================
namespace cfg {
constexpr int V = 17;
constexpr int D = 128;
constexpr int H = 256;
constexpr int E = 32;
constexpr float LN_EPS = 1e-5f;
constexpr int PAD = 20;

constexpr int NB_MAX = 16384;
constexpr int MROWS  = NB_MAX * V;     // 278528 = 2176 * 128

// fused-kernel smem layout (identical to R7)
constexpr int HT_OFF  = 0;
constexpr int R3_OFF  = HT_OFF + D * PAD;
constexpr int HST_OFF = R3_OFF;
constexpr int H2T_OFF = R3_OFF;
constexpr int XB_OFF  = R3_OFF;
constexpr int R2_OFF  = R3_OFF + H * PAD;
constexpr int Q_OFF   = R2_OFF;
constexpr int AG_OFF  = R2_OFF;
constexpr int EP_OFF  = R2_OFF;
constexpr int C2P_OFF = R2_OFF + D * PAD;
constexpr int R2_END  = C2P_OFF + D * V;

constexpr int MISC = R2_END;
constexpr int SX_OFF = MISC;
constexpr int SY_OFF = SX_OFF + V;
constexpr int MF_OFF = SY_OFF + V;
constexpr int IV_OFF = MF_OFF + V;
constexpr int HB_OFF = IV_OFF + V;
constexpr int DN_OFF = HB_OFF + V;
constexpr int RX_OFF = DN_OFF + V;
constexpr int RY_OFF = RX_OFF + E;
constexpr int VA_OFF = RY_OFF + E;
constexpr int SRX_OFF = VA_OFF + E;
constexpr int SRY_OFF = SRX_OFF + E;
constexpr int SVA_OFF = SRY_OFF + E;
constexpr int INT_OFF = SVA_OFF + E;
constexpr int I_DST = 0, I_SRC = 32, I_SSRC = 64, I_EORD = 96, I_CNT = 128, I_OFFA = 145;
constexpr int SMEM_FLOATS = INT_OFF + 163 + 13;
constexpr int SMEM_BYTES = SMEM_FLOATS * 4;
}  // namespace cfg

// ============================================================================
// Static device scratch
// ============================================================================
__device__ u64   g_hh[cfg::MROWS * cfg::D / 4];   // h hi, packed 4x bf16
__device__ u64   g_hl[cfg::MROWS * cfg::D / 4];   // h lo
__device__ u64   g_bh[512 * cfg::D / 4];          // W' (PQ weights, [cc][k]) hi
__device__ u64   g_bl[512 * cfg::D / 4];          // lo
__device__ float g_pq[(long long)cfg::MROWS * 512];

// ============================================================================
// packed fp32x2 helpers (fused kernel)
// ============================================================================
__device__ __forceinline__ u64 pk2(float x) {
    u64 r; asm("mov.b64 %0, {%1, %1};" : "=l"(r) : "f"(x)); return r;
}
__device__ __forceinline__ void fma2(u64& d, u64 a, u64 b) {
    asm("fma.rn.f32x2 %0, %1, %2, %0;" : "+l"(d) : "l"(a), "l"(b));
}
__device__ __forceinline__ float2 up2(u64 v) {
    float2 r; asm("mov.b64 {%0, %1}, %2;" : "=f"(r.x), "=f"(r.y) : "l"(v)); return r;
}

// bf16 split
__device__ __forceinline__ void bsplit(float a, unsigned short& hi, unsigned short& lo) {
    __nv_bfloat16 h = __float2bfloat16(a);
    float r = a - __bfloat162float(h);
    __nv_bfloat16 l = __float2bfloat16(r);
    hi = __bfloat16_as_ushort(h);
    lo = __bfloat16_as_ushort(l);
}

// ============================================================================
// Prep kernels
// ============================================================================
__global__ void prep_split_h(const float4* __restrict__ h4, int n4) {
    int i = blockIdx.x * 256 + threadIdx.x;
    if (i >= n4) return;
    float4 v = h4[i];
    unsigned short h0, l0, h1, l1, h2, l2, h3, l3;
    bsplit(v.x, h0, l0); bsplit(v.y, h1, l1);
    bsplit(v.z, h2, l2); bsplit(v.w, h3, l3);
    g_hh[i] = (u64)h0 | ((u64)h1 << 16) | ((u64)h2 << 32) | ((u64)h3 << 48);
    g_hl[i] = (u64)l0 | ((u64)l1 << 16) | ((u64)l2 << 32) | ((u64)l3 << 48);
}

// W'[k][cc] = cc<256 ? ew1[k][cc] : ew1[128+k][cc-256]; stored [cc][k]
__global__ void prep_w(const float* __restrict__ ew1) {
    int i = blockIdx.x * 256 + threadIdx.x;
    if (i >= 512 * 32) return;
    int cc = i >> 5;
    int k0 = (i & 31) * 4;
    int roff = (cc >= 256) ? 128 : 0;
    int col = cc & 255;
    u64 ph = 0, pl = 0;
    #pragma unroll
    for (int kk = 0; kk < 4; kk++) {
        float v = ew1[(long long)(k0 + kk + roff) * 256 + col];
        unsigned short hi, lo;
        bsplit(v, hi, lo);
        ph |= (u64)hi << (16 * kk);
        pl |= (u64)lo << (16 * kk);
    }
    g_bh[i] = ph;
    g_bl[i] = pl;
}

// ============================================================================
// Tensor-core GEMM via mma.sync (baseline PTX, works on sm_103 non-'a'):
// PQ[M,512] = h[M,128] @ W'[128,512], bf16 3-split, fp32 accumulate.
// CTA: 256 thr / 8 warps; tile 128(M) x 64(N); warp tile 16 x 64.
// ============================================================================
__global__ __launch_bounds__(256) void gemm_pq(int Mtot) {
    const int tid = threadIdx.x;
    const int wid = tid >> 5, lane = tid & 31;
    const int n0 = blockIdx.x * 64;
    const long long m0 = (long long)blockIdx.y * 128 + wid * 16;
    const int g = lane >> 2, t = lane & 3;

    float acc[8][4];
    #pragma unroll
    for (int i = 0; i < 8; i++)
        #pragma unroll
        for (int j = 0; j < 4; j++) acc[i][j] = 0.0f;

    const unsigned* Ah = (const unsigned*)g_hh;
    const unsigned* Al = (const unsigned*)g_hl;
    const unsigned* Bh = (const unsigned*)g_bh;
    const unsigned* Bl = (const unsigned*)g_bl;

    const long long r0 = m0 + g, r1 = m0 + g + 8;
    const bool v0 = r0 < Mtot, v1 = r1 < Mtot;

    #pragma unroll
    for (int pass = 0; pass < 3; pass++) {
        const unsigned* A = (pass == 2) ? Al : Ah;
        const unsigned* B = (pass == 1) ? Bl : Bh;
        #pragma unroll
        for (int ks = 0; ks < 8; ks++) {
            const int kk = ks * 8;   // u32 index (16 bf16 per k-step = 8 u32)
            unsigned a0 = 0, a1 = 0, a2 = 0, a3 = 0;
            if (v0) { a0 = A[r0 * 64 + kk + t]; a2 = A[r0 * 64 + kk + t + 4]; }
            if (v1) { a1 = A[r1 * 64 + kk + t]; a3 = A[r1 * 64 + kk + t + 4]; }
            #pragma unroll
            for (int nt = 0; nt < 8; nt++) {
                const int n = n0 + nt * 8 + g;
                unsigned b0 = B[n * 64 + kk + t];
                unsigned b1 = B[n * 64 + kk + t + 4];
                asm volatile(
                    "mma.sync.aligned.m16n8k16.row.col.f32.bf16.bf16.f32 "
                    "{%0,%1,%2,%3}, {%4,%5,%6,%7}, {%8,%9}, {%0,%1,%2,%3};"
                    : "+f"(acc[nt][0]), "+f"(acc[nt][1]),
                      "+f"(acc[nt][2]), "+f"(acc[nt][3])
                    : "r"(a0), "r"(a1), "r"(a2), "r"(a3), "r"(b0), "r"(b1));
            }
        }
    }
    // epilogue: c0,c1 = (row g, cols 2t,2t+1); c2,c3 = (row g+8, same cols)
    #pragma unroll
    for (int nt = 0; nt < 8; nt++) {
        const int col = n0 + nt * 8 + t * 2;
        if (v0) *reinterpret_cast<float2*>(g_pq + r0 * 512 + col) =
            make_float2(acc[nt][0], acc[nt][1]);
        if (v1) *reinterpret_cast<float2*>(g_pq + r1 * 512 + col) =
            make_float2(acc[nt][2], acc[nt][3]);
    }
}

// ============================================================================
// Fused kernel (R7 body; phase B replaced by PQ gmem reads)
// ============================================================================

template<int NU>
struct Acc2 {
    u64 a[2][NU];
    __device__ __forceinline__ void zero() {
        #pragma unroll
        for (int c = 0; c < 2; c++)
            #pragma unroll
            for (int i = 0; i < NU; i++) a[c][i] = 0ull;
    }
    __device__ __forceinline__ void step(const float* __restrict__ p, float2 w) {
        u64 r[NU];
        ulonglong2 t0 = *reinterpret_cast<const ulonglong2*>(p);
        ulonglong2 t1 = *reinterpret_cast<const ulonglong2*>(p + 4);
        r[0] = t0.x; r[1] = t0.y; r[2] = t1.x; r[3] = t1.y;
        if (NU == 5) r[NU - 1] = *reinterpret_cast<const u64*>(p + 8);
        u64 w0 = pk2(w.x), w1 = pk2(w.y);
        #pragma unroll
        for (int i = 0; i < NU; i++) { fma2(a[0][i], r[i], w0); fma2(a[1][i], r[i], w1); }
    }
    __device__ __forceinline__ float get(int c, int r) const {
        float2 f = up2(a[c][r >> 1]); return (r & 1) ? f.y : f.x;
    }
};

template<int RG>
__device__ __forceinline__ void phaseC2(float* sm, int cg, int kh,
                                        const float* __restrict__ ew2,
                                        const float* __restrict__ eb2) {
    using namespace cfg;
    constexpr int NU = RG ? 5 : 4;
    const int r0 = RG * 8, nval = RG ? 9 : 8;
    const int c = cg * 2;
    Acc2<NU> t; t.zero();
    const float* ab = sm + HST_OFF + (kh * 128) * PAD + r0;
    const float* wp = ew2 + (long long)(kh * 128) * D + c;
    #pragma unroll 4
    for (int k = 0; k < 128; k++)
        t.step(ab + k * PAD, *reinterpret_cast<const float2*>(wp + (long long)k * D));
    if (kh) {
        #pragma unroll
        for (int ci = 0; ci < 2; ci++)
            #pragma unroll
            for (int r = 0; r < nval; r++)
                sm[C2P_OFF + (c + ci) * V + r0 + r] = t.get(ci, r);
    }
    __syncthreads();
    if (!kh) {
        #pragma unroll
        for (int ci = 0; ci < 2; ci++) {
            const float b2 = eb2[c + ci];
            #pragma unroll
            for (int r = 0; r < nval; r++) {
                int v = r0 + r;
                float a = t.get(ci, r) + sm[C2P_OFF + (c + ci) * V + v]
                        + sm[DN_OFF + v] * b2;
                sm[AG_OFF + (c + ci) * PAD + v] = a * sm[IV_OFF + v];
            }
            if (RG) sm[AG_OFF + (c + ci) * PAD + 17] = 0.0f;
        }
    }
}

template<int RG>
__device__ __forceinline__ void phaseD(float* sm, int cg,
                                       const float* __restrict__ nw1,
                                       const float* __restrict__ nb1) {
    using namespace cfg;
    constexpr int NU = RG ? 5 : 4;
    const int r0 = RG * 8, nval = RG ? 9 : 8;
    const int c = cg * 2;
    Acc2<NU> t; t.zero();
    const float* ab = sm + HT_OFF + r0;
    const float* wp = nw1 + c;
    #pragma unroll 4
    for (int k = 0; k < 128; k++)
        t.step(ab + k * PAD, *reinterpret_cast<const float2*>(wp + (long long)k * H));
    const float* ab2 = sm + AG_OFF + r0;
    const float* wp2 = nw1 + (long long)128 * H + c;
    #pragma unroll 4
    for (int k = 0; k < 128; k++)
        t.step(ab2 + k * PAD, *reinterpret_cast<const float2*>(wp2 + (long long)k * H));
    #pragma unroll
    for (int ci = 0; ci < 2; ci++) {
        const float bb = nb1[c + ci];
        #pragma unroll
        for (int r = 0; r < nval; r++)
            sm[H2T_OFF + (c + ci) * PAD + r0 + r] = fmaxf(t.get(ci, r) + bb, 0.0f);
    }
}

template<int RG>
__device__ __forceinline__ void phaseE(float* sm, int cg, int kh,
                                       const float* __restrict__ nw2,
                                       const float* __restrict__ nb2) {
    using namespace cfg;
    constexpr int NU = RG ? 5 : 4;
    const int r0 = RG * 8, nval = RG ? 9 : 8;
    const int c = cg * 2;
    Acc2<NU> t; t.zero();
    const float* ab = sm + H2T_OFF + (kh * 128) * PAD + r0;
    const float* wp = nw2 + (long long)(kh * 128) * D + c;
    #pragma unroll 4
    for (int k = 0; k < 128; k++)
        t.step(ab + k * PAD, *reinterpret_cast<const float2*>(wp + (long long)k * D));
    if (kh) {
        #pragma unroll
        for (int ci = 0; ci < 2; ci++)
            #pragma unroll
            for (int r = 0; r < nval; r++)
                sm[EP_OFF + (c + ci) * V + r0 + r] = t.get(ci, r);
    }
    __syncthreads();
    if (!kh) {
        #pragma unroll
        for (int ci = 0; ci < 2; ci++) {
            const float b2 = nb2[c + ci];
            #pragma unroll
            for (int r = 0; r < nval; r++) {
                int v = r0 + r;
                float delta = t.get(ci, r) + sm[EP_OFF + (c + ci) * V + v] + b2;
                float xv = sm[HT_OFF + (c + ci) * PAD + v] + delta * sm[HB_OFF + v];
                sm[XB_OFF + v * D + c + ci] = xv;
            }
        }
    }
}

__global__ __launch_bounds__(256, 4) void graph_layer_kernel(
    const float* __restrict__ h, const float* __restrict__ xy,
    const void* __restrict__ jmask_raw, const void* __restrict__ edge_raw,
    const float* __restrict__ ew1, const float* __restrict__ eb1,
    const float* __restrict__ ew2, const float* __restrict__ eb2,
    const float* __restrict__ nw1, const float* __restrict__ nb1,
    const float* __restrict__ nw2, const float* __restrict__ nb2,
    const float* __restrict__ gamma, const float* __restrict__ beta,
    float* __restrict__ out)
{
    using namespace cfg;
    extern __shared__ float sm[];
    int* smi = reinterpret_cast<int*>(sm + INT_OFF);
    __shared__ int s_etype;
    __shared__ int s_mtype;

    const int n = blockIdx.x;
    const int tid = threadIdx.x;
    const int wrp = tid >> 5, lane = tid & 31;
    const long long nbase = (long long)n * V;

    if (tid == 0) {
        const unsigned* ew = (const unsigned*)edge_raw;
        unsigned odd_or = 0;
        #pragma unroll
        for (int i = 1; i < 2 * E; i += 2) odd_or |= ew[i];
        s_etype = (odd_or == 0) ? 1 : 0;
        const unsigned* mw = (const unsigned*)jmask_raw;
        bool all_i = true, all_f = true;
        #pragma unroll
        for (int i = 0; i < 64; i++) {
            unsigned w = mw[i];
            all_i = all_i && (w <= 1u);
            all_f = all_f && (w == 0u || w == 0x3F800000u);
        }
        s_mtype = all_i ? 1 : (all_f ? 2 : 0);
    }
    // h transpose + zero pad col 17
    {
        const float4* h4 = reinterpret_cast<const float4*>(h + nbase * D);
        for (int idx = tid; idx < V * D / 4; idx += 256) {
            int v = (idx * 4) / D, k4 = (idx * 4) % D;
            float4 t = h4[idx];
            sm[HT_OFF + (k4 + 0) * PAD + v] = t.x;
            sm[HT_OFF + (k4 + 1) * PAD + v] = t.y;
            sm[HT_OFF + (k4 + 2) * PAD + v] = t.z;
            sm[HT_OFF + (k4 + 3) * PAD + v] = t.w;
        }
        if (tid < D) sm[HT_OFF + tid * PAD + 17] = 0.0f;
    }
    if (tid < V) {
        sm[SX_OFF + tid] = xy[(nbase + tid) * 2 + 0];
        sm[SY_OFF + tid] = xy[(nbase + tid) * 2 + 1];
    }
    // Q columns from PQ gmem -> smem (thread owns column tid)
    {
        const float* qsrc = g_pq + nbase * 512 + 256 + tid;
        #pragma unroll
        for (int v = 0; v < V; v++)
            sm[Q_OFF + v * H + tid] = qsrc[(long long)v * 512];
    }
    __syncthreads();

    if (tid < V) {
        float mf;
        if (s_mtype == 0)
            mf = ((const unsigned char*)jmask_raw)[nbase + tid] ? 1.0f : 0.0f;
        else if (s_mtype == 1)
            mf = ((const int*)jmask_raw)[nbase + tid] ? 1.0f : 0.0f;
        else
            mf = (((const float*)jmask_raw)[nbase + tid] != 0.0f) ? 1.0f : 0.0f;
        sm[MF_OFF + tid] = mf;
    }
    if (tid < E) {
        int dv, sv;
        if (s_etype == 1) {
            const long long* e64 = (const long long*)edge_raw;
            dv = (int)e64[tid * 2 + 0];
            sv = (int)e64[tid * 2 + 1];
        } else {
            const int* e32 = (const int*)edge_raw;
            dv = e32[tid * 2 + 0];
            sv = e32[tid * 2 + 1];
        }
        smi[I_DST + tid] = dv;
        smi[I_SRC + tid] = sv;
    }
    __syncthreads();

    if (tid < E) {
        int dv = smi[I_DST + tid], sv = smi[I_SRC + tid];
        sm[RX_OFF + tid] = sm[SX_OFF + sv] - sm[SX_OFF + dv];
        sm[RY_OFF + tid] = sm[SY_OFF + sv] - sm[SY_OFF + dv];
        sm[VA_OFF + tid] = sm[MF_OFF + dv] * sm[MF_OFF + sv];
    }
    if (tid >= 64 && tid < 64 + V) {
        int v = tid - 64, c = 0;
        #pragma unroll
        for (int e = 0; e < E; e++) c += (smi[I_DST + e] == v);
        smi[I_CNT + v] = c;
    }
    __syncthreads();

    if (tid == 0) {
        int o = 0;
        #pragma unroll
        for (int v = 0; v < V; v++) { smi[I_OFFA + v] = o; o += smi[I_CNT + v]; }
        smi[I_OFFA + V] = o;
    }
    __syncthreads();

    if (tid < V) {
        int pos = smi[I_OFFA + tid];
        float dn = 0.0f;
        #pragma unroll
        for (int e = 0; e < E; e++) {
            if (smi[I_DST + e] == tid) {
                smi[I_EORD + pos++] = e;
                dn += sm[VA_OFF + e];
            }
        }
        sm[DN_OFF + tid] = dn;
        sm[IV_OFF + tid] = 1.0f / fmaxf(dn, 1.0f);
        sm[HB_OFF + tid] = dn > 0.0f ? 1.0f : 0.0f;
    }
    __syncthreads();

    if (tid < E) {
        int e = smi[I_EORD + tid];
        smi[I_SSRC + tid] = smi[I_SRC + e];
        sm[SRX_OFF + tid] = sm[RX_OFF + e];
        sm[SRY_OFF + tid] = sm[RY_OFF + e];
        sm[SVA_OFF + tid] = sm[VA_OFF + e];
    }
    __syncthreads();

    // ------- Phase C: hsumT[j][v]; P read from PQ gmem -------
    {
        const int j = tid;
        const float b1v = eb1[j];
        const float wx = ew1[(long long)(2 * D) * H + j];
        const float wy = ew1[(long long)(2 * D + 1) * H + j];
        const float* psrc = g_pq + nbase * 512 + j;
        int o0 = smi[I_OFFA + 0];
        #pragma unroll
        for (int v = 0; v < V; v++) {
            const int o1 = smi[I_OFFA + v + 1];
            const float pv = psrc[(long long)v * 512];
            float acc = 0.0f;
            for (int i = o0; i < o1; i++) {
                const int sv = smi[I_SSRC + i];
                float hid = pv + sm[Q_OFF + sv * H + j]
                          + sm[SRX_OFF + i] * wx + sm[SRY_OFF + i] * wy + b1v;
                acc = fmaf(fmaxf(hid, 0.0f), sm[SVA_OFF + i], acc);
            }
            sm[HST_OFF + j * PAD + v] = acc;
            o0 = o1;
        }
        sm[HST_OFF + j * PAD + 17] = 0.0f;
    }
    __syncthreads();

    // ------- Phase C2 -------
    {
        const int rgw = wrp & 1;
        const int kh = (wrp >> 1) & 1;
        const int cg = (wrp >> 2) * 32 + lane;
        if (rgw == 0) phaseC2<0>(sm, cg, kh, ew2, eb2);
        else          phaseC2<1>(sm, cg, kh, ew2, eb2);
    }
    __syncthreads();

    // ------- Phase D -------
    {
        const int rgw = wrp & 1;
        const int cg = (wrp >> 1) * 32 + lane;
        if (rgw == 0) phaseD<0>(sm, cg, nw1, nb1);
        else          phaseD<1>(sm, cg, nw1, nb1);
    }
    __syncthreads();

    // ------- Phase E -------
    {
        const int rgw = wrp & 1;
        const int kh = (wrp >> 1) & 1;
        const int cg = (wrp >> 2) * 32 + lane;
        if (rgw == 0) phaseE<0>(sm, cg, kh, nw2, nb2);
        else          phaseE<1>(sm, cg, kh, nw2, nb2);
    }
    __syncthreads();

    // ------- Phase F: LayerNorm + gamma/beta + mask -------
    {
        const float g0 = gamma[lane], g1 = gamma[lane + 32],
                    g2 = gamma[lane + 64], g3 = gamma[lane + 96];
        const float b0 = beta[lane], b1 = beta[lane + 32],
                    b2 = beta[lane + 64], b3 = beta[lane + 96];
        for (int v = wrp; v < V; v += 8) {
            float x0 = sm[XB_OFF + v * D + lane];
            float x1 = sm[XB_OFF + v * D + lane + 32];
            float x2 = sm[XB_OFF + v * D + lane + 64];
            float x3 = sm[XB_OFF + v * D + lane + 96];
            float s = x0 + x1 + x2 + x3;
            #pragma unroll
            for (int off = 16; off > 0; off >>= 1)
                s += __shfl_xor_sync(0xffffffffu, s, off);
            float mu = s * (1.0f / 128.0f);
            float d0 = x0 - mu, d1 = x1 - mu, d2 = x2 - mu, d3 = x3 - mu;
            float q = d0 * d0 + d1 * d1 + d2 * d2 + d3 * d3;
            #pragma unroll
            for (int off = 16; off > 0; off >>= 1)
                q += __shfl_xor_sync(0xffffffffu, q, off);
            float rstd = rsqrtf(q * (1.0f / 128.0f) + LN_EPS);
            float m = sm[MF_OFF + v];
            long long base = (nbase + v) * D;
            out[base + lane]      = (d0 * rstd * g0 + b0) * m;
            out[base + lane + 32] = (d1 * rstd * g1 + b1) * m;
            out[base + lane + 64] = (d2 * rstd * g2 + b2) * m;
            out[base + lane + 96] = (d3 * rstd * g3 + b3) * m;
        }
    }
}

// ============================================================================
// Launch
// ============================================================================
extern "C" void kernel_launch(void* const* d_in, const int* in_sizes, int n_in,
                              void* d_out, int out_size) {
    using namespace cfg;
    const float* h = (const float*)d_in[0];
    const float* xy = (const float*)d_in[1];
    const void* jmask = d_in[2];
    const void* edge = d_in[3];
    const float* ew1 = (const float*)d_in[4];
    const float* eb1 = (const float*)d_in[5];
    const float* ew2 = (const float*)d_in[6];
    const float* eb2 = (const float*)d_in[7];
    const float* nw1 = (const float*)d_in[8];
    const float* nb1 = (const float*)d_in[9];
    const float* nw2 = (const float*)d_in[10];
    const float* nb2 = (const float*)d_in[11];
    const float* gamma = (const float*)d_in[12];
    const float* beta = (const float*)d_in[13];
    float* out = (float*)d_out;

    const int nbatch = in_sizes[0] / (V * D);
    const int Mtot = nbatch * V;

    // prep: bf16 hi/lo splits
    {
        int n4 = Mtot * (D / 4);
        prep_split_h<<<(n4 + 255) / 256, 256>>>((const float4*)h, n4);
        prep_w<<<(512 * 32 + 255) / 256, 256>>>(ew1);
    }
    // tensor-core GEMM: PQ = h @ W'
    {
        int mtiles = (Mtot + 127) / 128;
        gemm_pq<<<dim3(8, mtiles), 256>>>(Mtot);
    }
    // fused remainder
    cudaFuncSetAttribute(graph_layer_kernel,
                         cudaFuncAttributeMaxDynamicSharedMemorySize, SMEM_BYTES);
    graph_layer_kernel<<<nbatch, 256, SMEM_BYTES>>>(
        h, xy, jmask, edge, ew1, eb1, ew2, eb2,
        nw1, nb1, nw2, nb2, gamma, beta, out);
}

// round 16
// speedup vs baseline: 1.2534x; 1.2534x over previous
#include <cuda_runtime.h>
#include <cuda_bf16.h>

typedef unsigned long long u64;

// ============================================================================
// Problem constants
// ============================================================================
namespace cfg {
constexpr int V = 17;
constexpr int D = 128;
constexpr int H = 256;
constexpr int E = 32;
constexpr float LN_EPS = 1e-5f;
constexpr int PAD = 20;

constexpr int NB_MAX = 16384;
constexpr int MROWS  = NB_MAX * V;     // 278528 = 256 * 1088

// fused-kernel smem layout (identical to R7)
constexpr int HT_OFF  = 0;
constexpr int R3_OFF  = HT_OFF + D * PAD;
constexpr int HST_OFF = R3_OFF;
constexpr int H2T_OFF = R3_OFF;
constexpr int XB_OFF  = R3_OFF;
constexpr int R2_OFF  = R3_OFF + H * PAD;
constexpr int Q_OFF   = R2_OFF;
constexpr int AG_OFF  = R2_OFF;
constexpr int EP_OFF  = R2_OFF;
constexpr int C2P_OFF = R2_OFF + D * PAD;
constexpr int R2_END  = C2P_OFF + D * V;

constexpr int MISC = R2_END;
constexpr int SX_OFF = MISC;
constexpr int SY_OFF = SX_OFF + V;
constexpr int MF_OFF = SY_OFF + V;
constexpr int IV_OFF = MF_OFF + V;
constexpr int HB_OFF = IV_OFF + V;
constexpr int DN_OFF = HB_OFF + V;
constexpr int RX_OFF = DN_OFF + V;
constexpr int RY_OFF = RX_OFF + E;
constexpr int VA_OFF = RY_OFF + E;
constexpr int SRX_OFF = VA_OFF + E;
constexpr int SRY_OFF = SRX_OFF + E;
constexpr int SVA_OFF = SRY_OFF + E;
constexpr int INT_OFF = SVA_OFF + E;
constexpr int I_DST = 0, I_SRC = 32, I_SSRC = 64, I_EORD = 96, I_CNT = 128, I_OFFA = 145;
constexpr int SMEM_FLOATS = INT_OFF + 163 + 13;
constexpr int SMEM_BYTES = SMEM_FLOATS * 4;
}  // namespace cfg

// ============================================================================
// Static device scratch
// ============================================================================
__device__ u64   g_hh[cfg::MROWS * cfg::D / 4];   // h hi, packed 4x bf16
__device__ u64   g_hl[cfg::MROWS * cfg::D / 4];   // h lo
__device__ u64   g_bh[512 * cfg::D / 4];          // W' (PQ weights, [cc][k]) hi
__device__ u64   g_bl[512 * cfg::D / 4];          // lo
__device__ float g_pq[(long long)cfg::MROWS * 512];

// ============================================================================
// packed fp32x2 helpers (fused kernel)
// ============================================================================
__device__ __forceinline__ u64 pk2(float x) {
    u64 r; asm("mov.b64 %0, {%1, %1};" : "=l"(r) : "f"(x)); return r;
}
__device__ __forceinline__ void fma2(u64& d, u64 a, u64 b) {
    asm("fma.rn.f32x2 %0, %1, %2, %0;" : "+l"(d) : "l"(a), "l"(b));
}
__device__ __forceinline__ float2 up2(u64 v) {
    float2 r; asm("mov.b64 {%0, %1}, %2;" : "=f"(r.x), "=f"(r.y) : "l"(v)); return r;
}

// bf16 split
__device__ __forceinline__ void bsplit(float a, unsigned short& hi, unsigned short& lo) {
    __nv_bfloat16 h = __float2bfloat16(a);
    float r = a - __bfloat162float(h);
    __nv_bfloat16 l = __float2bfloat16(r);
    hi = __bfloat16_as_ushort(h);
    lo = __bfloat16_as_ushort(l);
}

// ============================================================================
// Prep kernels
// ============================================================================
__global__ void prep_split_h(const float4* __restrict__ h4, int n4) {
    int i = blockIdx.x * 256 + threadIdx.x;
    if (i >= n4) return;
    float4 v = h4[i];
    unsigned short h0, l0, h1, l1, h2, l2, h3, l3;
    bsplit(v.x, h0, l0); bsplit(v.y, h1, l1);
    bsplit(v.z, h2, l2); bsplit(v.w, h3, l3);
    g_hh[i] = (u64)h0 | ((u64)h1 << 16) | ((u64)h2 << 32) | ((u64)h3 << 48);
    g_hl[i] = (u64)l0 | ((u64)l1 << 16) | ((u64)l2 << 32) | ((u64)l3 << 48);
}

// W'[k][cc] = cc<256 ? ew1[k][cc] : ew1[128+k][cc-256]; stored [cc][k]
__global__ void prep_w(const float* __restrict__ ew1) {
    int i = blockIdx.x * 256 + threadIdx.x;
    if (i >= 512 * 32) return;
    int cc = i >> 5;
    int k0 = (i & 31) * 4;
    int roff = (cc >= 256) ? 128 : 0;
    int col = cc & 255;
    u64 ph = 0, pl = 0;
    #pragma unroll
    for (int kk = 0; kk < 4; kk++) {
        float v = ew1[(long long)(k0 + kk + roff) * 256 + col];
        unsigned short hi, lo;
        bsplit(v, hi, lo);
        ph |= (u64)hi << (16 * kk);
        pl |= (u64)lo << (16 * kk);
    }
    g_bh[i] = ph;
    g_bl[i] = pl;
}

// ============================================================================
// Tensor-core GEMM via mma.sync: PQ[M,512] = h[M,128] @ W'[128,512]
// bf16 3-term split (ah*bh + ah*bl + al*bh), fp32 accumulate.
// CTA: 8 warps; warp tile 32(M) x 64(N); CTA tile 256 x 64.
// ks-outer loop: A hi/lo + B hi/lo fragments loaded once per k-step.
// ============================================================================
#define MMA_BF16(ac, A0, A1, A2, A3, B0, B1)                                   \
    asm volatile(                                                              \
        "mma.sync.aligned.m16n8k16.row.col.f32.bf16.bf16.f32 "                 \
        "{%0,%1,%2,%3}, {%4,%5,%6,%7}, {%8,%9}, {%0,%1,%2,%3};"                \
        : "+f"((ac)[0]), "+f"((ac)[1]), "+f"((ac)[2]), "+f"((ac)[3])           \
        : "r"(A0), "r"(A1), "r"(A2), "r"(A3), "r"(B0), "r"(B1))

__global__ __launch_bounds__(256, 2) void gemm_pq(int Mtot) {
    const int tid = threadIdx.x;
    const int wid = tid >> 5, lane = tid & 31;
    const int n0 = blockIdx.x * 64;
    const long long m0 = (long long)blockIdx.y * 256 + wid * 32;
    const int g = lane >> 2, t = lane & 3;

    float acc0[8][4], acc1[8][4];
    #pragma unroll
    for (int i = 0; i < 8; i++)
        #pragma unroll
        for (int j = 0; j < 4; j++) { acc0[i][j] = 0.0f; acc1[i][j] = 0.0f; }

    const unsigned* __restrict__ Ah = (const unsigned*)g_hh;
    const unsigned* __restrict__ Al = (const unsigned*)g_hl;
    const unsigned* __restrict__ Bh = (const unsigned*)g_bh;
    const unsigned* __restrict__ Bl = (const unsigned*)g_bl;

    const long long r0 = m0 + g,      r1 = m0 + g + 8;       // m-block 0
    const long long r2 = m0 + 16 + g, r3 = m0 + 16 + g + 8;  // m-block 1
    const bool v0 = r0 < Mtot, v1 = r1 < Mtot, v2 = r2 < Mtot, v3 = r3 < Mtot;

    #pragma unroll
    for (int ks = 0; ks < 8; ks++) {
        const int kk = ks * 8;   // u32 index within 64-u32 row
        // A fragments: hi & lo for both m-blocks (16 LDG)
        unsigned ah0 = 0, ah1 = 0, ah2 = 0, ah3 = 0;
        unsigned al0 = 0, al1 = 0, al2 = 0, al3 = 0;
        unsigned ch0 = 0, ch1 = 0, ch2 = 0, ch3 = 0;
        unsigned cl0 = 0, cl1 = 0, cl2 = 0, cl3 = 0;
        if (v0) { ah0 = Ah[r0 * 64 + kk + t]; ah2 = Ah[r0 * 64 + kk + t + 4];
                  al0 = Al[r0 * 64 + kk + t]; al2 = Al[r0 * 64 + kk + t + 4]; }
        if (v1) { ah1 = Ah[r1 * 64 + kk + t]; ah3 = Ah[r1 * 64 + kk + t + 4];
                  al1 = Al[r1 * 64 + kk + t]; al3 = Al[r1 * 64 + kk + t + 4]; }
        if (v2) { ch0 = Ah[r2 * 64 + kk + t]; ch2 = Ah[r2 * 64 + kk + t + 4];
                  cl0 = Al[r2 * 64 + kk + t]; cl2 = Al[r2 * 64 + kk + t + 4]; }
        if (v3) { ch1 = Ah[r3 * 64 + kk + t]; ch3 = Ah[r3 * 64 + kk + t + 4];
                  cl1 = Al[r3 * 64 + kk + t]; cl3 = Al[r3 * 64 + kk + t + 4]; }
        #pragma unroll
        for (int nt = 0; nt < 8; nt++) {
            const int n = n0 + nt * 8 + g;
            const unsigned bh0 = Bh[n * 64 + kk + t];
            const unsigned bh1 = Bh[n * 64 + kk + t + 4];
            const unsigned bl0 = Bl[n * 64 + kk + t];
            const unsigned bl1 = Bl[n * 64 + kk + t + 4];
            // m-block 0: ah*bh + ah*bl + al*bh
            MMA_BF16(acc0[nt], ah0, ah1, ah2, ah3, bh0, bh1);
            MMA_BF16(acc0[nt], ah0, ah1, ah2, ah3, bl0, bl1);
            MMA_BF16(acc0[nt], al0, al1, al2, al3, bh0, bh1);
            // m-block 1
            MMA_BF16(acc1[nt], ch0, ch1, ch2, ch3, bh0, bh1);
            MMA_BF16(acc1[nt], ch0, ch1, ch2, ch3, bl0, bl1);
            MMA_BF16(acc1[nt], cl0, cl1, cl2, cl3, bh0, bh1);
        }
    }
    // epilogue: c0,c1 = (row g, cols 2t,2t+1); c2,c3 = (row g+8, same cols)
    #pragma unroll
    for (int nt = 0; nt < 8; nt++) {
        const int col = n0 + nt * 8 + t * 2;
        if (v0) *reinterpret_cast<float2*>(g_pq + r0 * 512 + col) =
            make_float2(acc0[nt][0], acc0[nt][1]);
        if (v1) *reinterpret_cast<float2*>(g_pq + r1 * 512 + col) =
            make_float2(acc0[nt][2], acc0[nt][3]);
        if (v2) *reinterpret_cast<float2*>(g_pq + r2 * 512 + col) =
            make_float2(acc1[nt][0], acc1[nt][1]);
        if (v3) *reinterpret_cast<float2*>(g_pq + r3 * 512 + col) =
            make_float2(acc1[nt][2], acc1[nt][3]);
    }
}

// ============================================================================
// Fused kernel (R7 body; phase B replaced by PQ gmem reads)
// ============================================================================

template<int NU>
struct Acc2 {
    u64 a[2][NU];
    __device__ __forceinline__ void zero() {
        #pragma unroll
        for (int c = 0; c < 2; c++)
            #pragma unroll
            for (int i = 0; i < NU; i++) a[c][i] = 0ull;
    }
    __device__ __forceinline__ void step(const float* __restrict__ p, float2 w) {
        u64 r[NU];
        ulonglong2 t0 = *reinterpret_cast<const ulonglong2*>(p);
        ulonglong2 t1 = *reinterpret_cast<const ulonglong2*>(p + 4);
        r[0] = t0.x; r[1] = t0.y; r[2] = t1.x; r[3] = t1.y;
        if (NU == 5) r[NU - 1] = *reinterpret_cast<const u64*>(p + 8);
        u64 w0 = pk2(w.x), w1 = pk2(w.y);
        #pragma unroll
        for (int i = 0; i < NU; i++) { fma2(a[0][i], r[i], w0); fma2(a[1][i], r[i], w1); }
    }
    __device__ __forceinline__ float get(int c, int r) const {
        float2 f = up2(a[c][r >> 1]); return (r & 1) ? f.y : f.x;
    }
};

template<int RG>
__device__ __forceinline__ void phaseC2(float* sm, int cg, int kh,
                                        const float* __restrict__ ew2,
                                        const float* __restrict__ eb2) {
    using namespace cfg;
    constexpr int NU = RG ? 5 : 4;
    const int r0 = RG * 8, nval = RG ? 9 : 8;
    const int c = cg * 2;
    Acc2<NU> t; t.zero();
    const float* ab = sm + HST_OFF + (kh * 128) * PAD + r0;
    const float* wp = ew2 + (long long)(kh * 128) * D + c;
    #pragma unroll 4
    for (int k = 0; k < 128; k++)
        t.step(ab + k * PAD, *reinterpret_cast<const float2*>(wp + (long long)k * D));
    if (kh) {
        #pragma unroll
        for (int ci = 0; ci < 2; ci++)
            #pragma unroll
            for (int r = 0; r < nval; r++)
                sm[C2P_OFF + (c + ci) * V + r0 + r] = t.get(ci, r);
    }
    __syncthreads();
    if (!kh) {
        #pragma unroll
        for (int ci = 0; ci < 2; ci++) {
            const float b2 = eb2[c + ci];
            #pragma unroll
            for (int r = 0; r < nval; r++) {
                int v = r0 + r;
                float a = t.get(ci, r) + sm[C2P_OFF + (c + ci) * V + v]
                        + sm[DN_OFF + v] * b2;
                sm[AG_OFF + (c + ci) * PAD + v] = a * sm[IV_OFF + v];
            }
            if (RG) sm[AG_OFF + (c + ci) * PAD + 17] = 0.0f;
        }
    }
}

template<int RG>
__device__ __forceinline__ void phaseD(float* sm, int cg,
                                       const float* __restrict__ nw1,
                                       const float* __restrict__ nb1) {
    using namespace cfg;
    constexpr int NU = RG ? 5 : 4;
    const int r0 = RG * 8, nval = RG ? 9 : 8;
    const int c = cg * 2;
    Acc2<NU> t; t.zero();
    const float* ab = sm + HT_OFF + r0;
    const float* wp = nw1 + c;
    #pragma unroll 4
    for (int k = 0; k < 128; k++)
        t.step(ab + k * PAD, *reinterpret_cast<const float2*>(wp + (long long)k * H));
    const float* ab2 = sm + AG_OFF + r0;
    const float* wp2 = nw1 + (long long)128 * H + c;
    #pragma unroll 4
    for (int k = 0; k < 128; k++)
        t.step(ab2 + k * PAD, *reinterpret_cast<const float2*>(wp2 + (long long)k * H));
    #pragma unroll
    for (int ci = 0; ci < 2; ci++) {
        const float bb = nb1[c + ci];
        #pragma unroll
        for (int r = 0; r < nval; r++)
            sm[H2T_OFF + (c + ci) * PAD + r0 + r] = fmaxf(t.get(ci, r) + bb, 0.0f);
    }
}

template<int RG>
__device__ __forceinline__ void phaseE(float* sm, int cg, int kh,
                                       const float* __restrict__ nw2,
                                       const float* __restrict__ nb2) {
    using namespace cfg;
    constexpr int NU = RG ? 5 : 4;
    const int r0 = RG * 8, nval = RG ? 9 : 8;
    const int c = cg * 2;
    Acc2<NU> t; t.zero();
    const float* ab = sm + H2T_OFF + (kh * 128) * PAD + r0;
    const float* wp = nw2 + (long long)(kh * 128) * D + c;
    #pragma unroll 4
    for (int k = 0; k < 128; k++)
        t.step(ab + k * PAD, *reinterpret_cast<const float2*>(wp + (long long)k * D));
    if (kh) {
        #pragma unroll
        for (int ci = 0; ci < 2; ci++)
            #pragma unroll
            for (int r = 0; r < nval; r++)
                sm[EP_OFF + (c + ci) * V + r0 + r] = t.get(ci, r);
    }
    __syncthreads();
    if (!kh) {
        #pragma unroll
        for (int ci = 0; ci < 2; ci++) {
            const float b2 = nb2[c + ci];
            #pragma unroll
            for (int r = 0; r < nval; r++) {
                int v = r0 + r;
                float delta = t.get(ci, r) + sm[EP_OFF + (c + ci) * V + v] + b2;
                float xv = sm[HT_OFF + (c + ci) * PAD + v] + delta * sm[HB_OFF + v];
                sm[XB_OFF + v * D + c + ci] = xv;
            }
        }
    }
}

__global__ __launch_bounds__(256, 4) void graph_layer_kernel(
    const float* __restrict__ h, const float* __restrict__ xy,
    const void* __restrict__ jmask_raw, const void* __restrict__ edge_raw,
    const float* __restrict__ ew1, const float* __restrict__ eb1,
    const float* __restrict__ ew2, const float* __restrict__ eb2,
    const float* __restrict__ nw1, const float* __restrict__ nb1,
    const float* __restrict__ nw2, const float* __restrict__ nb2,
    const float* __restrict__ gamma, const float* __restrict__ beta,
    float* __restrict__ out)
{
    using namespace cfg;
    extern __shared__ float sm[];
    int* smi = reinterpret_cast<int*>(sm + INT_OFF);
    __shared__ int s_etype;
    __shared__ int s_mtype;

    const int n = blockIdx.x;
    const int tid = threadIdx.x;
    const int wrp = tid >> 5, lane = tid & 31;
    const long long nbase = (long long)n * V;

    if (tid == 0) {
        const unsigned* ew = (const unsigned*)edge_raw;
        unsigned odd_or = 0;
        #pragma unroll
        for (int i = 1; i < 2 * E; i += 2) odd_or |= ew[i];
        s_etype = (odd_or == 0) ? 1 : 0;
        const unsigned* mw = (const unsigned*)jmask_raw;
        bool all_i = true, all_f = true;
        #pragma unroll
        for (int i = 0; i < 64; i++) {
            unsigned w = mw[i];
            all_i = all_i && (w <= 1u);
            all_f = all_f && (w == 0u || w == 0x3F800000u);
        }
        s_mtype = all_i ? 1 : (all_f ? 2 : 0);
    }
    // h transpose + zero pad col 17
    {
        const float4* h4 = reinterpret_cast<const float4*>(h + nbase * D);
        for (int idx = tid; idx < V * D / 4; idx += 256) {
            int v = (idx * 4) / D, k4 = (idx * 4) % D;
            float4 t = h4[idx];
            sm[HT_OFF + (k4 + 0) * PAD + v] = t.x;
            sm[HT_OFF + (k4 + 1) * PAD + v] = t.y;
            sm[HT_OFF + (k4 + 2) * PAD + v] = t.z;
            sm[HT_OFF + (k4 + 3) * PAD + v] = t.w;
        }
        if (tid < D) sm[HT_OFF + tid * PAD + 17] = 0.0f;
    }
    if (tid < V) {
        sm[SX_OFF + tid] = xy[(nbase + tid) * 2 + 0];
        sm[SY_OFF + tid] = xy[(nbase + tid) * 2 + 1];
    }
    // Q columns from PQ gmem -> smem (thread owns column tid)
    {
        const float* qsrc = g_pq + nbase * 512 + 256 + tid;
        #pragma unroll
        for (int v = 0; v < V; v++)
            sm[Q_OFF + v * H + tid] = qsrc[(long long)v * 512];
    }
    __syncthreads();

    if (tid < V) {
        float mf;
        if (s_mtype == 0)
            mf = ((const unsigned char*)jmask_raw)[nbase + tid] ? 1.0f : 0.0f;
        else if (s_mtype == 1)
            mf = ((const int*)jmask_raw)[nbase + tid] ? 1.0f : 0.0f;
        else
            mf = (((const float*)jmask_raw)[nbase + tid] != 0.0f) ? 1.0f : 0.0f;
        sm[MF_OFF + tid] = mf;
    }
    if (tid < E) {
        int dv, sv;
        if (s_etype == 1) {
            const long long* e64 = (const long long*)edge_raw;
            dv = (int)e64[tid * 2 + 0];
            sv = (int)e64[tid * 2 + 1];
        } else {
            const int* e32 = (const int*)edge_raw;
            dv = e32[tid * 2 + 0];
            sv = e32[tid * 2 + 1];
        }
        smi[I_DST + tid] = dv;
        smi[I_SRC + tid] = sv;
    }
    __syncthreads();

    if (tid < E) {
        int dv = smi[I_DST + tid], sv = smi[I_SRC + tid];
        sm[RX_OFF + tid] = sm[SX_OFF + sv] - sm[SX_OFF + dv];
        sm[RY_OFF + tid] = sm[SY_OFF + sv] - sm[SY_OFF + dv];
        sm[VA_OFF + tid] = sm[MF_OFF + dv] * sm[MF_OFF + sv];
    }
    if (tid >= 64 && tid < 64 + V) {
        int v = tid - 64, c = 0;
        #pragma unroll
        for (int e = 0; e < E; e++) c += (smi[I_DST + e] == v);
        smi[I_CNT + v] = c;
    }
    __syncthreads();

    if (tid == 0) {
        int o = 0;
        #pragma unroll
        for (int v = 0; v < V; v++) { smi[I_OFFA + v] = o; o += smi[I_CNT + v]; }
        smi[I_OFFA + V] = o;
    }
    __syncthreads();

    if (tid < V) {
        int pos = smi[I_OFFA + tid];
        float dn = 0.0f;
        #pragma unroll
        for (int e = 0; e < E; e++) {
            if (smi[I_DST + e] == tid) {
                smi[I_EORD + pos++] = e;
                dn += sm[VA_OFF + e];
            }
        }
        sm[DN_OFF + tid] = dn;
        sm[IV_OFF + tid] = 1.0f / fmaxf(dn, 1.0f);
        sm[HB_OFF + tid] = dn > 0.0f ? 1.0f : 0.0f;
    }
    __syncthreads();

    if (tid < E) {
        int e = smi[I_EORD + tid];
        smi[I_SSRC + tid] = smi[I_SRC + e];
        sm[SRX_OFF + tid] = sm[RX_OFF + e];
        sm[SRY_OFF + tid] = sm[RY_OFF + e];
        sm[SVA_OFF + tid] = sm[VA_OFF + e];
    }
    __syncthreads();

    // ------- Phase C: hsumT[j][v]; P read from PQ gmem -------
    {
        const int j = tid;
        const float b1v = eb1[j];
        const float wx = ew1[(long long)(2 * D) * H + j];
        const float wy = ew1[(long long)(2 * D + 1) * H + j];
        const float* psrc = g_pq + nbase * 512 + j;
        int o0 = smi[I_OFFA + 0];
        #pragma unroll
        for (int v = 0; v < V; v++) {
            const int o1 = smi[I_OFFA + v + 1];
            const float pv = psrc[(long long)v * 512];
            float acc = 0.0f;
            for (int i = o0; i < o1; i++) {
                const int sv = smi[I_SSRC + i];
                float hid = pv + sm[Q_OFF + sv * H + j]
                          + sm[SRX_OFF + i] * wx + sm[SRY_OFF + i] * wy + b1v;
                acc = fmaf(fmaxf(hid, 0.0f), sm[SVA_OFF + i], acc);
            }
            sm[HST_OFF + j * PAD + v] = acc;
            o0 = o1;
        }
        sm[HST_OFF + j * PAD + 17] = 0.0f;
    }
    __syncthreads();

    // ------- Phase C2 -------
    {
        const int rgw = wrp & 1;
        const int kh = (wrp >> 1) & 1;
        const int cg = (wrp >> 2) * 32 + lane;
        if (rgw == 0) phaseC2<0>(sm, cg, kh, ew2, eb2);
        else          phaseC2<1>(sm, cg, kh, ew2, eb2);
    }
    __syncthreads();

    // ------- Phase D -------
    {
        const int rgw = wrp & 1;
        const int cg = (wrp >> 1) * 32 + lane;
        if (rgw == 0) phaseD<0>(sm, cg, nw1, nb1);
        else          phaseD<1>(sm, cg, nw1, nb1);
    }
    __syncthreads();

    // ------- Phase E -------
    {
        const int rgw = wrp & 1;
        const int kh = (wrp >> 1) & 1;
        const int cg = (wrp >> 2) * 32 + lane;
        if (rgw == 0) phaseE<0>(sm, cg, kh, nw2, nb2);
        else          phaseE<1>(sm, cg, kh, nw2, nb2);
    }
    __syncthreads();

    // ------- Phase F: LayerNorm + gamma/beta + mask -------
    {
        const float g0 = gamma[lane], g1 = gamma[lane + 32],
                    g2 = gamma[lane + 64], g3 = gamma[lane + 96];
        const float b0 = beta[lane], b1 = beta[lane + 32],
                    b2 = beta[lane + 64], b3 = beta[lane + 96];
        for (int v = wrp; v < V; v += 8) {
            float x0 = sm[XB_OFF + v * D + lane];
            float x1 = sm[XB_OFF + v * D + lane + 32];
            float x2 = sm[XB_OFF + v * D + lane + 64];
            float x3 = sm[XB_OFF + v * D + lane + 96];
            float s = x0 + x1 + x2 + x3;
            #pragma unroll
            for (int off = 16; off > 0; off >>= 1)
                s += __shfl_xor_sync(0xffffffffu, s, off);
            float mu = s * (1.0f / 128.0f);
            float d0 = x0 - mu, d1 = x1 - mu, d2 = x2 - mu, d3 = x3 - mu;
            float q = d0 * d0 + d1 * d1 + d2 * d2 + d3 * d3;
            #pragma unroll
            for (int off = 16; off > 0; off >>= 1)
                q += __shfl_xor_sync(0xffffffffu, q, off);
            float rstd = rsqrtf(q * (1.0f / 128.0f) + LN_EPS);
            float m = sm[MF_OFF + v];
            long long base = (nbase + v) * D;
            out[base + lane]      = (d0 * rstd * g0 + b0) * m;
            out[base + lane + 32] = (d1 * rstd * g1 + b1) * m;
            out[base + lane + 64] = (d2 * rstd * g2 + b2) * m;
            out[base + lane + 96] = (d3 * rstd * g3 + b3) * m;
        }
    }
}

// ============================================================================
// Launch
// ============================================================================
extern "C" void kernel_launch(void* const* d_in, const int* in_sizes, int n_in,
                              void* d_out, int out_size) {
    using namespace cfg;
    const float* h = (const float*)d_in[0];
    const float* xy = (const float*)d_in[1];
    const void* jmask = d_in[2];
    const void* edge = d_in[3];
    const float* ew1 = (const float*)d_in[4];
    const float* eb1 = (const float*)d_in[5];
    const float* ew2 = (const float*)d_in[6];
    const float* eb2 = (const float*)d_in[7];
    const float* nw1 = (const float*)d_in[8];
    const float* nb1 = (const float*)d_in[9];
    const float* nw2 = (const float*)d_in[10];
    const float* nb2 = (const float*)d_in[11];
    const float* gamma = (const float*)d_in[12];
    const float* beta = (const float*)d_in[13];
    float* out = (float*)d_out;

    const int nbatch = in_sizes[0] / (V * D);
    const int Mtot = nbatch * V;

    // prep: bf16 hi/lo splits
    {
        int n4 = Mtot * (D / 4);
        prep_split_h<<<(n4 + 255) / 256, 256>>>((const float4*)h, n4);
        prep_w<<<(512 * 32 + 255) / 256, 256>>>(ew1);
    }
    // tensor-core GEMM: PQ = h @ W'
    {
        int mtiles = (Mtot + 255) / 256;
        gemm_pq<<<dim3(8, mtiles), 256>>>(Mtot);
    }
    // fused remainder
    cudaFuncSetAttribute(graph_layer_kernel,
                         cudaFuncAttributeMaxDynamicSharedMemorySize, SMEM_BYTES);
    graph_layer_kernel<<<nbatch, 256, SMEM_BYTES>>>(
        h, xy, jmask, edge, ew1, eb1, ew2, eb2,
        nw1, nb1, nw2, nb2, gamma, beta, out);
}

// round 17
// speedup vs baseline: 1.3287x; 1.0601x over previous
#include <cuda_runtime.h>
#include <cuda_bf16.h>

typedef unsigned long long u64;

// ============================================================================
// Problem constants
// ============================================================================
namespace cfg {
constexpr int V = 17;
constexpr int D = 128;
constexpr int H = 256;
constexpr int E = 32;
constexpr float LN_EPS = 1e-5f;
constexpr int PAD = 20;

constexpr int NB_MAX = 16384;
constexpr int MROWS  = NB_MAX * V;     // 278528 = 32 * 8704

// fused-kernel smem layout (identical to R7)
constexpr int HT_OFF  = 0;
constexpr int R3_OFF  = HT_OFF + D * PAD;
constexpr int HST_OFF = R3_OFF;
constexpr int H2T_OFF = R3_OFF;
constexpr int XB_OFF  = R3_OFF;
constexpr int R2_OFF  = R3_OFF + H * PAD;
constexpr int Q_OFF   = R2_OFF;
constexpr int AG_OFF  = R2_OFF;
constexpr int EP_OFF  = R2_OFF;
constexpr int C2P_OFF = R2_OFF + D * PAD;
constexpr int R2_END  = C2P_OFF + D * V;

constexpr int MISC = R2_END;
constexpr int SX_OFF = MISC;
constexpr int SY_OFF = SX_OFF + V;
constexpr int MF_OFF = SY_OFF + V;
constexpr int IV_OFF = MF_OFF + V;
constexpr int HB_OFF = IV_OFF + V;
constexpr int DN_OFF = HB_OFF + V;
constexpr int RX_OFF = DN_OFF + V;
constexpr int RY_OFF = RX_OFF + E;
constexpr int VA_OFF = RY_OFF + E;
constexpr int SRX_OFF = VA_OFF + E;
constexpr int SRY_OFF = SRX_OFF + E;
constexpr int SVA_OFF = SRY_OFF + E;
constexpr int INT_OFF = SVA_OFF + E;
constexpr int I_DST = 0, I_SRC = 32, I_SSRC = 64, I_EORD = 96, I_CNT = 128, I_OFFA = 145;
constexpr int SMEM_FLOATS = INT_OFF + 163 + 13;
constexpr int SMEM_BYTES = SMEM_FLOATS * 4;
}  // namespace cfg

// ============================================================================
// Static device scratch
// ============================================================================
__device__ u64   g_bh[512 * cfg::D / 4];          // W' (PQ weights, [cc][k]) hi
__device__ u64   g_bl[512 * cfg::D / 4];          // lo
__device__ float g_pq[(long long)cfg::MROWS * 512];

// ============================================================================
// packed fp32x2 helpers (fused kernel)
// ============================================================================
__device__ __forceinline__ u64 pk2(float x) {
    u64 r; asm("mov.b64 %0, {%1, %1};" : "=l"(r) : "f"(x)); return r;
}
__device__ __forceinline__ void fma2(u64& d, u64 a, u64 b) {
    asm("fma.rn.f32x2 %0, %1, %2, %0;" : "+l"(d) : "l"(a), "l"(b));
}
__device__ __forceinline__ float2 up2(u64 v) {
    float2 r; asm("mov.b64 {%0, %1}, %2;" : "=f"(r.x), "=f"(r.y) : "l"(v)); return r;
}

// bf16 split (scalar, for prep_w)
__device__ __forceinline__ void bsplit(float a, unsigned short& hi, unsigned short& lo) {
    __nv_bfloat16 h = __float2bfloat16(a);
    float r = a - __bfloat162float(h);
    __nv_bfloat16 l = __float2bfloat16(r);
    hi = __bfloat16_as_ushort(h);
    lo = __bfloat16_as_ushort(l);
}

// in-register split of float2 -> packed bf16x2 hi/lo fragments
__device__ __forceinline__ void split2(float2 v, unsigned& hi, unsigned& lo) {
    __nv_bfloat16 hx = __float2bfloat16(v.x);
    __nv_bfloat16 hy = __float2bfloat16(v.y);
    float rx = v.x - __bfloat162float(hx);
    float ry = v.y - __bfloat162float(hy);
    __nv_bfloat16 lx = __float2bfloat16(rx);
    __nv_bfloat16 ly = __float2bfloat16(ry);
    unsigned short hxs = __bfloat16_as_ushort(hx), hys = __bfloat16_as_ushort(hy);
    unsigned short lxs = __bfloat16_as_ushort(lx), lys = __bfloat16_as_ushort(ly);
    hi = (unsigned)hxs | ((unsigned)hys << 16);
    lo = (unsigned)lxs | ((unsigned)lys << 16);
}

// ============================================================================
// Prep kernel (weights only; tiny)
// W'[k][cc] = cc<256 ? ew1[k][cc] : ew1[128+k][cc-256]; stored [cc][k]
// ============================================================================
__global__ void prep_w(const float* __restrict__ ew1) {
    int i = blockIdx.x * 256 + threadIdx.x;
    if (i >= 512 * 32) return;
    int cc = i >> 5;
    int k0 = (i & 31) * 4;
    int roff = (cc >= 256) ? 128 : 0;
    int col = cc & 255;
    u64 ph = 0, pl = 0;
    #pragma unroll
    for (int kk = 0; kk < 4; kk++) {
        float v = ew1[(long long)(k0 + kk + roff) * 256 + col];
        unsigned short hi, lo;
        bsplit(v, hi, lo);
        ph |= (u64)hi << (16 * kk);
        pl |= (u64)lo << (16 * kk);
    }
    g_bh[i] = ph;
    g_bl[i] = pl;
}

// ============================================================================
// Tensor-core GEMM via mma.sync: PQ[M,512] = h[M,128] @ W'[128,512]
// A loaded fp32 from h and split in-register (no h prep pass).
// CTA = 32 M-rows x 512 N (8 warps, wid = n-block); A traffic 1x.
// bf16 3-term split (ah*bh + ah*bl + al*bh), fp32 accumulate.
// ============================================================================
#define MMA_BF16(ac, A0, A1, A2, A3, B0, B1)                                   \
    asm volatile(                                                              \
        "mma.sync.aligned.m16n8k16.row.col.f32.bf16.bf16.f32 "                 \
        "{%0,%1,%2,%3}, {%4,%5,%6,%7}, {%8,%9}, {%0,%1,%2,%3};"                \
        : "+f"((ac)[0]), "+f"((ac)[1]), "+f"((ac)[2]), "+f"((ac)[3])           \
        : "r"(A0), "r"(A1), "r"(A2), "r"(A3), "r"(B0), "r"(B1))

__global__ __launch_bounds__(256, 2) void gemm_pq(const float* __restrict__ h,
                                                  int Mtot) {
    const int tid = threadIdx.x;
    const int wid = tid >> 5, lane = tid & 31;
    const int n0 = wid * 64;
    const long long m0 = (long long)blockIdx.x * 32;
    const int g = lane >> 2, t = lane & 3;

    float acc0[8][4], acc1[8][4];
    #pragma unroll
    for (int i = 0; i < 8; i++)
        #pragma unroll
        for (int j = 0; j < 4; j++) { acc0[i][j] = 0.0f; acc1[i][j] = 0.0f; }

    const unsigned* __restrict__ Bh = (const unsigned*)g_bh;
    const unsigned* __restrict__ Bl = (const unsigned*)g_bl;

    const long long r0 = m0 + g,      r1 = m0 + g + 8;       // m-block 0
    const long long r2 = m0 + 16 + g, r3 = m0 + 16 + g + 8;  // m-block 1
    const bool v0 = r0 < Mtot, v1 = r1 < Mtot, v2 = r2 < Mtot, v3 = r3 < Mtot;
    const float2 z2 = make_float2(0.0f, 0.0f);

    #pragma unroll
    for (int ks = 0; ks < 8; ks++) {
        const int k0 = ks * 16;
        // A fragments (fp32 load + in-register split), both m-blocks
        float2 p00 = v0 ? *reinterpret_cast<const float2*>(h + r0 * 128 + k0 + 2 * t)     : z2;
        float2 p02 = v0 ? *reinterpret_cast<const float2*>(h + r0 * 128 + k0 + 8 + 2 * t) : z2;
        float2 p10 = v1 ? *reinterpret_cast<const float2*>(h + r1 * 128 + k0 + 2 * t)     : z2;
        float2 p12 = v1 ? *reinterpret_cast<const float2*>(h + r1 * 128 + k0 + 8 + 2 * t) : z2;
        float2 p20 = v2 ? *reinterpret_cast<const float2*>(h + r2 * 128 + k0 + 2 * t)     : z2;
        float2 p22 = v2 ? *reinterpret_cast<const float2*>(h + r2 * 128 + k0 + 8 + 2 * t) : z2;
        float2 p30 = v3 ? *reinterpret_cast<const float2*>(h + r3 * 128 + k0 + 2 * t)     : z2;
        float2 p32 = v3 ? *reinterpret_cast<const float2*>(h + r3 * 128 + k0 + 8 + 2 * t) : z2;

        unsigned ah0, ah1, ah2, ah3, al0, al1, al2, al3;
        unsigned ch0, ch1, ch2, ch3, cl0, cl1, cl2, cl3;
        split2(p00, ah0, al0); split2(p10, ah1, al1);
        split2(p02, ah2, al2); split2(p12, ah3, al3);
        split2(p20, ch0, cl0); split2(p30, ch1, cl1);
        split2(p22, ch2, cl2); split2(p32, ch3, cl3);

        const int kk = ks * 8;   // u32 index within 64-u32 B row
        #pragma unroll
        for (int nt = 0; nt < 8; nt++) {
            const int n = n0 + nt * 8 + g;
            const unsigned bh0 = Bh[n * 64 + kk + t];
            const unsigned bh1 = Bh[n * 64 + kk + t + 4];
            const unsigned bl0 = Bl[n * 64 + kk + t];
            const unsigned bl1 = Bl[n * 64 + kk + t + 4];
            // m-block 0: ah*bh + ah*bl + al*bh
            MMA_BF16(acc0[nt], ah0, ah1, ah2, ah3, bh0, bh1);
            MMA_BF16(acc0[nt], ah0, ah1, ah2, ah3, bl0, bl1);
            MMA_BF16(acc0[nt], al0, al1, al2, al3, bh0, bh1);
            // m-block 1
            MMA_BF16(acc1[nt], ch0, ch1, ch2, ch3, bh0, bh1);
            MMA_BF16(acc1[nt], ch0, ch1, ch2, ch3, bl0, bl1);
            MMA_BF16(acc1[nt], cl0, cl1, cl2, cl3, bh0, bh1);
        }
    }
    // epilogue: c0,c1 = (row g, cols 2t,2t+1); c2,c3 = (row g+8, same cols)
    #pragma unroll
    for (int nt = 0; nt < 8; nt++) {
        const int col = n0 + nt * 8 + t * 2;
        if (v0) *reinterpret_cast<float2*>(g_pq + r0 * 512 + col) =
            make_float2(acc0[nt][0], acc0[nt][1]);
        if (v1) *reinterpret_cast<float2*>(g_pq + r1 * 512 + col) =
            make_float2(acc0[nt][2], acc0[nt][3]);
        if (v2) *reinterpret_cast<float2*>(g_pq + r2 * 512 + col) =
            make_float2(acc1[nt][0], acc1[nt][1]);
        if (v3) *reinterpret_cast<float2*>(g_pq + r3 * 512 + col) =
            make_float2(acc1[nt][2], acc1[nt][3]);
    }
}

// ============================================================================
// Fused kernel (R7 body; phase B replaced by PQ gmem reads)
// ============================================================================

template<int NU>
struct Acc2 {
    u64 a[2][NU];
    __device__ __forceinline__ void zero() {
        #pragma unroll
        for (int c = 0; c < 2; c++)
            #pragma unroll
            for (int i = 0; i < NU; i++) a[c][i] = 0ull;
    }
    __device__ __forceinline__ void step(const float* __restrict__ p, float2 w) {
        u64 r[NU];
        ulonglong2 t0 = *reinterpret_cast<const ulonglong2*>(p);
        ulonglong2 t1 = *reinterpret_cast<const ulonglong2*>(p + 4);
        r[0] = t0.x; r[1] = t0.y; r[2] = t1.x; r[3] = t1.y;
        if (NU == 5) r[NU - 1] = *reinterpret_cast<const u64*>(p + 8);
        u64 w0 = pk2(w.x), w1 = pk2(w.y);
        #pragma unroll
        for (int i = 0; i < NU; i++) { fma2(a[0][i], r[i], w0); fma2(a[1][i], r[i], w1); }
    }
    __device__ __forceinline__ float get(int c, int r) const {
        float2 f = up2(a[c][r >> 1]); return (r & 1) ? f.y : f.x;
    }
};

template<int RG>
__device__ __forceinline__ void phaseC2(float* sm, int cg, int kh,
                                        const float* __restrict__ ew2,
                                        const float* __restrict__ eb2) {
    using namespace cfg;
    constexpr int NU = RG ? 5 : 4;
    const int r0 = RG * 8, nval = RG ? 9 : 8;
    const int c = cg * 2;
    Acc2<NU> t; t.zero();
    const float* ab = sm + HST_OFF + (kh * 128) * PAD + r0;
    const float* wp = ew2 + (long long)(kh * 128) * D + c;
    #pragma unroll 4
    for (int k = 0; k < 128; k++)
        t.step(ab + k * PAD, *reinterpret_cast<const float2*>(wp + (long long)k * D));
    if (kh) {
        #pragma unroll
        for (int ci = 0; ci < 2; ci++)
            #pragma unroll
            for (int r = 0; r < nval; r++)
                sm[C2P_OFF + (c + ci) * V + r0 + r] = t.get(ci, r);
    }
    __syncthreads();
    if (!kh) {
        #pragma unroll
        for (int ci = 0; ci < 2; ci++) {
            const float b2 = eb2[c + ci];
            #pragma unroll
            for (int r = 0; r < nval; r++) {
                int v = r0 + r;
                float a = t.get(ci, r) + sm[C2P_OFF + (c + ci) * V + v]
                        + sm[DN_OFF + v] * b2;
                sm[AG_OFF + (c + ci) * PAD + v] = a * sm[IV_OFF + v];
            }
            if (RG) sm[AG_OFF + (c + ci) * PAD + 17] = 0.0f;
        }
    }
}

template<int RG>
__device__ __forceinline__ void phaseD(float* sm, int cg,
                                       const float* __restrict__ nw1,
                                       const float* __restrict__ nb1) {
    using namespace cfg;
    constexpr int NU = RG ? 5 : 4;
    const int r0 = RG * 8, nval = RG ? 9 : 8;
    const int c = cg * 2;
    Acc2<NU> t; t.zero();
    const float* ab = sm + HT_OFF + r0;
    const float* wp = nw1 + c;
    #pragma unroll 4
    for (int k = 0; k < 128; k++)
        t.step(ab + k * PAD, *reinterpret_cast<const float2*>(wp + (long long)k * H));
    const float* ab2 = sm + AG_OFF + r0;
    const float* wp2 = nw1 + (long long)128 * H + c;
    #pragma unroll 4
    for (int k = 0; k < 128; k++)
        t.step(ab2 + k * PAD, *reinterpret_cast<const float2*>(wp2 + (long long)k * H));
    #pragma unroll
    for (int ci = 0; ci < 2; ci++) {
        const float bb = nb1[c + ci];
        #pragma unroll
        for (int r = 0; r < nval; r++)
            sm[H2T_OFF + (c + ci) * PAD + r0 + r] = fmaxf(t.get(ci, r) + bb, 0.0f);
    }
}

template<int RG>
__device__ __forceinline__ void phaseE(float* sm, int cg, int kh,
                                       const float* __restrict__ nw2,
                                       const float* __restrict__ nb2) {
    using namespace cfg;
    constexpr int NU = RG ? 5 : 4;
    const int r0 = RG * 8, nval = RG ? 9 : 8;
    const int c = cg * 2;
    Acc2<NU> t; t.zero();
    const float* ab = sm + H2T_OFF + (kh * 128) * PAD + r0;
    const float* wp = nw2 + (long long)(kh * 128) * D + c;
    #pragma unroll 4
    for (int k = 0; k < 128; k++)
        t.step(ab + k * PAD, *reinterpret_cast<const float2*>(wp + (long long)k * D));
    if (kh) {
        #pragma unroll
        for (int ci = 0; ci < 2; ci++)
            #pragma unroll
            for (int r = 0; r < nval; r++)
                sm[EP_OFF + (c + ci) * V + r0 + r] = t.get(ci, r);
    }
    __syncthreads();
    if (!kh) {
        #pragma unroll
        for (int ci = 0; ci < 2; ci++) {
            const float b2 = nb2[c + ci];
            #pragma unroll
            for (int r = 0; r < nval; r++) {
                int v = r0 + r;
                float delta = t.get(ci, r) + sm[EP_OFF + (c + ci) * V + v] + b2;
                float xv = sm[HT_OFF + (c + ci) * PAD + v] + delta * sm[HB_OFF + v];
                sm[XB_OFF + v * D + c + ci] = xv;
            }
        }
    }
}

__global__ __launch_bounds__(256, 4) void graph_layer_kernel(
    const float* __restrict__ h, const float* __restrict__ xy,
    const void* __restrict__ jmask_raw, const void* __restrict__ edge_raw,
    const float* __restrict__ ew1, const float* __restrict__ eb1,
    const float* __restrict__ ew2, const float* __restrict__ eb2,
    const float* __restrict__ nw1, const float* __restrict__ nb1,
    const float* __restrict__ nw2, const float* __restrict__ nb2,
    const float* __restrict__ gamma, const float* __restrict__ beta,
    float* __restrict__ out)
{
    using namespace cfg;
    extern __shared__ float sm[];
    int* smi = reinterpret_cast<int*>(sm + INT_OFF);
    __shared__ int s_etype;
    __shared__ int s_mtype;

    const int n = blockIdx.x;
    const int tid = threadIdx.x;
    const int wrp = tid >> 5, lane = tid & 31;
    const long long nbase = (long long)n * V;

    if (tid == 0) {
        const unsigned* ew = (const unsigned*)edge_raw;
        unsigned odd_or = 0;
        #pragma unroll
        for (int i = 1; i < 2 * E; i += 2) odd_or |= ew[i];
        s_etype = (odd_or == 0) ? 1 : 0;
        const unsigned* mw = (const unsigned*)jmask_raw;
        bool all_i = true, all_f = true;
        #pragma unroll
        for (int i = 0; i < 64; i++) {
            unsigned w = mw[i];
            all_i = all_i && (w <= 1u);
            all_f = all_f && (w == 0u || w == 0x3F800000u);
        }
        s_mtype = all_i ? 1 : (all_f ? 2 : 0);
    }
    // h transpose + zero pad col 17
    {
        const float4* h4 = reinterpret_cast<const float4*>(h + nbase * D);
        for (int idx = tid; idx < V * D / 4; idx += 256) {
            int v = (idx * 4) / D, k4 = (idx * 4) % D;
            float4 t = h4[idx];
            sm[HT_OFF + (k4 + 0) * PAD + v] = t.x;
            sm[HT_OFF + (k4 + 1) * PAD + v] = t.y;
            sm[HT_OFF + (k4 + 2) * PAD + v] = t.z;
            sm[HT_OFF + (k4 + 3) * PAD + v] = t.w;
        }
        if (tid < D) sm[HT_OFF + tid * PAD + 17] = 0.0f;
    }
    if (tid < V) {
        sm[SX_OFF + tid] = xy[(nbase + tid) * 2 + 0];
        sm[SY_OFF + tid] = xy[(nbase + tid) * 2 + 1];
    }
    // Q columns from PQ gmem -> smem (thread owns column tid)
    {
        const float* qsrc = g_pq + nbase * 512 + 256 + tid;
        #pragma unroll
        for (int v = 0; v < V; v++)
            sm[Q_OFF + v * H + tid] = qsrc[(long long)v * 512];
    }
    __syncthreads();

    if (tid < V) {
        float mf;
        if (s_mtype == 0)
            mf = ((const unsigned char*)jmask_raw)[nbase + tid] ? 1.0f : 0.0f;
        else if (s_mtype == 1)
            mf = ((const int*)jmask_raw)[nbase + tid] ? 1.0f : 0.0f;
        else
            mf = (((const float*)jmask_raw)[nbase + tid] != 0.0f) ? 1.0f : 0.0f;
        sm[MF_OFF + tid] = mf;
    }
    if (tid < E) {
        int dv, sv;
        if (s_etype == 1) {
            const long long* e64 = (const long long*)edge_raw;
            dv = (int)e64[tid * 2 + 0];
            sv = (int)e64[tid * 2 + 1];
        } else {
            const int* e32 = (const int*)edge_raw;
            dv = e32[tid * 2 + 0];
            sv = e32[tid * 2 + 1];
        }
        smi[I_DST + tid] = dv;
        smi[I_SRC + tid] = sv;
    }
    __syncthreads();

    if (tid < E) {
        int dv = smi[I_DST + tid], sv = smi[I_SRC + tid];
        sm[RX_OFF + tid] = sm[SX_OFF + sv] - sm[SX_OFF + dv];
        sm[RY_OFF + tid] = sm[SY_OFF + sv] - sm[SY_OFF + dv];
        sm[VA_OFF + tid] = sm[MF_OFF + dv] * sm[MF_OFF + sv];
    }
    if (tid >= 64 && tid < 64 + V) {
        int v = tid - 64, c = 0;
        #pragma unroll
        for (int e = 0; e < E; e++) c += (smi[I_DST + e] == v);
        smi[I_CNT + v] = c;
    }
    __syncthreads();

    if (tid == 0) {
        int o = 0;
        #pragma unroll
        for (int v = 0; v < V; v++) { smi[I_OFFA + v] = o; o += smi[I_CNT + v]; }
        smi[I_OFFA + V] = o;
    }
    __syncthreads();

    if (tid < V) {
        int pos = smi[I_OFFA + tid];
        float dn = 0.0f;
        #pragma unroll
        for (int e = 0; e < E; e++) {
            if (smi[I_DST + e] == tid) {
                smi[I_EORD + pos++] = e;
                dn += sm[VA_OFF + e];
            }
        }
        sm[DN_OFF + tid] = dn;
        sm[IV_OFF + tid] = 1.0f / fmaxf(dn, 1.0f);
        sm[HB_OFF + tid] = dn > 0.0f ? 1.0f : 0.0f;
    }
    __syncthreads();

    if (tid < E) {
        int e = smi[I_EORD + tid];
        smi[I_SSRC + tid] = smi[I_SRC + e];
        sm[SRX_OFF + tid] = sm[RX_OFF + e];
        sm[SRY_OFF + tid] = sm[RY_OFF + e];
        sm[SVA_OFF + tid] = sm[VA_OFF + e];
    }
    __syncthreads();

    // ------- Phase C: hsumT[j][v]; P read from PQ gmem -------
    {
        const int j = tid;
        const float b1v = eb1[j];
        const float wx = ew1[(long long)(2 * D) * H + j];
        const float wy = ew1[(long long)(2 * D + 1) * H + j];
        const float* psrc = g_pq + nbase * 512 + j;
        int o0 = smi[I_OFFA + 0];
        #pragma unroll
        for (int v = 0; v < V; v++) {
            const int o1 = smi[I_OFFA + v + 1];
            const float pv = psrc[(long long)v * 512];
            float acc = 0.0f;
            for (int i = o0; i < o1; i++) {
                const int sv = smi[I_SSRC + i];
                float hid = pv + sm[Q_OFF + sv * H + j]
                          + sm[SRX_OFF + i] * wx + sm[SRY_OFF + i] * wy + b1v;
                acc = fmaf(fmaxf(hid, 0.0f), sm[SVA_OFF + i], acc);
            }
            sm[HST_OFF + j * PAD + v] = acc;
            o0 = o1;
        }
        sm[HST_OFF + j * PAD + 17] = 0.0f;
    }
    __syncthreads();

    // ------- Phase C2 -------
    {
        const int rgw = wrp & 1;
        const int kh = (wrp >> 1) & 1;
        const int cg = (wrp >> 2) * 32 + lane;
        if (rgw == 0) phaseC2<0>(sm, cg, kh, ew2, eb2);
        else          phaseC2<1>(sm, cg, kh, ew2, eb2);
    }
    __syncthreads();

    // ------- Phase D -------
    {
        const int rgw = wrp & 1;
        const int cg = (wrp >> 1) * 32 + lane;
        if (rgw == 0) phaseD<0>(sm, cg, nw1, nb1);
        else          phaseD<1>(sm, cg, nw1, nb1);
    }
    __syncthreads();

    // ------- Phase E -------
    {
        const int rgw = wrp & 1;
        const int kh = (wrp >> 1) & 1;
        const int cg = (wrp >> 2) * 32 + lane;
        if (rgw == 0) phaseE<0>(sm, cg, kh, nw2, nb2);
        else          phaseE<1>(sm, cg, kh, nw2, nb2);
    }
    __syncthreads();

    // ------- Phase F: LayerNorm + gamma/beta + mask -------
    {
        const float g0 = gamma[lane], g1 = gamma[lane + 32],
                    g2 = gamma[lane + 64], g3 = gamma[lane + 96];
        const float b0 = beta[lane], b1 = beta[lane + 32],
                    b2 = beta[lane + 64], b3 = beta[lane + 96];
        for (int v = wrp; v < V; v += 8) {
            float x0 = sm[XB_OFF + v * D + lane];
            float x1 = sm[XB_OFF + v * D + lane + 32];
            float x2 = sm[XB_OFF + v * D + lane + 64];
            float x3 = sm[XB_OFF + v * D + lane + 96];
            float s = x0 + x1 + x2 + x3;
            #pragma unroll
            for (int off = 16; off > 0; off >>= 1)
                s += __shfl_xor_sync(0xffffffffu, s, off);
            float mu = s * (1.0f / 128.0f);
            float d0 = x0 - mu, d1 = x1 - mu, d2 = x2 - mu, d3 = x3 - mu;
            float q = d0 * d0 + d1 * d1 + d2 * d2 + d3 * d3;
            #pragma unroll
            for (int off = 16; off > 0; off >>= 1)
                q += __shfl_xor_sync(0xffffffffu, q, off);
            float rstd = rsqrtf(q * (1.0f / 128.0f) + LN_EPS);
            float m = sm[MF_OFF + v];
            long long base = (nbase + v) * D;
            out[base + lane]      = (d0 * rstd * g0 + b0) * m;
            out[base + lane + 32] = (d1 * rstd * g1 + b1) * m;
            out[base + lane + 64] = (d2 * rstd * g2 + b2) * m;
            out[base + lane + 96] = (d3 * rstd * g3 + b3) * m;
        }
    }
}

// ============================================================================
// Launch
// ============================================================================
extern "C" void kernel_launch(void* const* d_in, const int* in_sizes, int n_in,
                              void* d_out, int out_size) {
    using namespace cfg;
    const float* h = (const float*)d_in[0];
    const float* xy = (const float*)d_in[1];
    const void* jmask = d_in[2];
    const void* edge = d_in[3];
    const float* ew1 = (const float*)d_in[4];
    const float* eb1 = (const float*)d_in[5];
    const float* ew2 = (const float*)d_in[6];
    const float* eb2 = (const float*)d_in[7];
    const float* nw1 = (const float*)d_in[8];
    const float* nb1 = (const float*)d_in[9];
    const float* nw2 = (const float*)d_in[10];
    const float* nb2 = (const float*)d_in[11];
    const float* gamma = (const float*)d_in[12];
    const float* beta = (const float*)d_in[13];
    float* out = (float*)d_out;

    const int nbatch = in_sizes[0] / (V * D);
    const int Mtot = nbatch * V;

    // prep: weight bf16 hi/lo split (tiny)
    prep_w<<<(512 * 32 + 255) / 256, 256>>>(ew1);

    // tensor-core GEMM: PQ = h @ W'  (A fp32 direct, split in-register)
    {
        int mtiles = (Mtot + 31) / 32;
        gemm_pq<<<mtiles, 256>>>(h, Mtot);
    }
    // fused remainder
    cudaFuncSetAttribute(graph_layer_kernel,
                         cudaFuncAttributeMaxDynamicSharedMemorySize, SMEM_BYTES);
    graph_layer_kernel<<<nbatch, 256, SMEM_BYTES>>>(
        h, xy, jmask, edge, ew1, eb1, ew2, eb2,
        nw1, nb1, nw2, nb2, gamma, beta, out);
}